// round 6
// baseline (speedup 1.0000x reference)
#include <cuda_runtime.h>
#include <cuda_bf16.h>
#include <math.h>

#define D 4096
#define H 2
#define HD (D / H)     // 2048
#define E 8192

// Scratch (device globals — no allocations allowed). Fully overwritten every run.
__device__ float g_x[2 * D];        // embeddings / attention input
__device__ float g_qkv[2 * 3 * D];  // packed qkv
__device__ float g_o[2 * D];        // attention output (pre out-proj)
__device__ float g_x1[2 * D];       // after residual 1
__device__ float g_h[2 * D];        // ffn hidden
__device__ float g_x2[2 * D];       // after residual 2
__device__ float g_g[2 * E];        // expert hidden

// ---------------------------------------------------------------------------
// Stage 0: per-task embeddings  x[l][i] = relu(ray[l]*emb_w[i] + emb_b[i])
// ---------------------------------------------------------------------------
__global__ void k_embed(const float* __restrict__ ray,
                        const float* __restrict__ w1, const float* __restrict__ b1,
                        const float* __restrict__ w2, const float* __restrict__ b2) {
    int i = blockIdx.x * blockDim.x + threadIdx.x;
    if (i < D) {
        float r0 = __ldg(ray + 0);
        float r1 = __ldg(ray + 1);
        g_x[i]     = fmaxf(r0 * w1[i] + b1[i], 0.0f);
        g_x[D + i] = fmaxf(r1 * w2[i] + b2[i], 0.0f);
    }
}

// ---------------------------------------------------------------------------
// Persistent grid-strided 2-row GEMV (K = 4096 fixed).
//  - x vectors live in SHARED memory (loaded once per block; 32 KB) so the
//    register file holds only the weight double-buffer -> ptxas keeps the
//    software pipeline (next row's 4 LDG.128 in flight during current FMAs).
//  - grid-strided row loop (grid = 4*148) for balanced persistent waves.
//  - parity-double-buffered reduction slots: one __syncthreads per row,
//    epilogue (thread 0) overlaps next row's loads.
// ---------------------------------------------------------------------------
template <bool RELU, bool RESID>
__global__ void __launch_bounds__(256, 4)
k_gemv_p(const float* __restrict__ W,
         const float* __restrict__ b,
         const float* __restrict__ xin,     // [2][D]
         const float* __restrict__ resid,   // [2][N] or null
         float* __restrict__ out,           // [2][N]
         int N) {
    __shared__ float4 sx0[D / 4];           // 16 KB
    __shared__ float4 sx1[D / 4];           // 16 KB
    __shared__ float red[2][2][8];          // [parity][vec][warp]

    const int tid  = threadIdx.x;
    const int warp = tid >> 5, lane = tid & 31;

    // Fill shared x (both sequence positions).
    const float4* __restrict__ x0 = reinterpret_cast<const float4*>(xin);
    const float4* __restrict__ x1 = reinterpret_cast<const float4*>(xin + D);
#pragma unroll
    for (int t = 0; t < 4; ++t) {
        sx0[t * 256 + tid] = x0[t * 256 + tid];
        sx1[t * 256 + tid] = x1[t * 256 + tid];
    }
    __syncthreads();

    int j = blockIdx.x;
    const int stride = gridDim.x;
    if (j >= N) return;

    // Prologue: first row's weights.
    float4 wc[4];
    {
        const float4* __restrict__ wr = reinterpret_cast<const float4*>(W + (size_t)j * D);
#pragma unroll
        for (int t = 0; t < 4; ++t) wc[t] = wr[t * 256 + tid];
    }

    int p = 0;
    for (; j < N; j += stride) {
        const int jn = j + stride;

        // Prefetch next row while current row computes.
        float4 wn[4];
        if (jn < N) {
            const float4* __restrict__ wr = reinterpret_cast<const float4*>(W + (size_t)jn * D);
#pragma unroll
            for (int t = 0; t < 4; ++t) wn[t] = wr[t * 256 + tid];
        }

        float a0 = 0.0f, a1 = 0.0f;
#pragma unroll
        for (int t = 0; t < 4; ++t) {
            float4 xa = sx0[t * 256 + tid];
            float4 xb = sx1[t * 256 + tid];
            a0 += wc[t].x * xa.x + wc[t].y * xa.y + wc[t].z * xa.z + wc[t].w * xa.w;
            a1 += wc[t].x * xb.x + wc[t].y * xb.y + wc[t].z * xb.z + wc[t].w * xb.w;
        }
#pragma unroll
        for (int off = 16; off; off >>= 1) {
            a0 += __shfl_xor_sync(0xFFFFFFFFu, a0, off);
            a1 += __shfl_xor_sync(0xFFFFFFFFu, a1, off);
        }
        if (lane == 0) { red[p][0][warp] = a0; red[p][1][warp] = a1; }
        __syncthreads();
        if (tid == 0) {
            float r0 = 0.0f, r1 = 0.0f;
#pragma unroll
            for (int w = 0; w < 8; ++w) { r0 += red[p][0][w]; r1 += red[p][1][w]; }
            float bb = b ? b[j] : 0.0f;
            r0 += bb; r1 += bb;
            if (RESID) { r0 += resid[j]; r1 += resid[N + j]; }
            if (RELU)  { r0 = fmaxf(r0, 0.0f); r1 = fmaxf(r1, 0.0f); }
            out[j]     = r0;
            out[N + j] = r1;
        }
        p ^= 1;

        if (jn < N) {
#pragma unroll
            for (int t = 0; t < 4; ++t) wc[t] = wn[t];
        }
    }
}

// ---------------------------------------------------------------------------
// Stage 2: multi-head attention on the 2-token sequence (tiny; one block).
// ---------------------------------------------------------------------------
__global__ void k_attn() {
    __shared__ float s_scores[8];  // index: h*4 + l*2 + m
    __shared__ float s_attn[8];
    const int tid = threadIdx.x;          // 256 threads = 8 warps
    const int warp = tid >> 5, lane = tid & 31;

    // one warp per (h, l, m) combination
    const int h = warp >> 2, l = (warp >> 1) & 1, m = warp & 1;
    const float* __restrict__ q = g_qkv + l * 3 * D + h * HD;
    const float* __restrict__ k = g_qkv + m * 3 * D + D + h * HD;
    float acc = 0.0f;
#pragma unroll 4
    for (int i = lane; i < HD; i += 32) acc += q[i] * k[i];
#pragma unroll
    for (int off = 16; off; off >>= 1) acc += __shfl_xor_sync(0xFFFFFFFFu, acc, off);
    if (lane == 0) s_scores[warp] = acc * rsqrtf((float)HD);
    __syncthreads();

    if (tid < 4) {  // (h, l) pairs: softmax over m (2 elements)
        int hh = tid >> 1, ll = tid & 1;
        float s0v = s_scores[hh * 4 + ll * 2 + 0];
        float s1v = s_scores[hh * 4 + ll * 2 + 1];
        float mx = fmaxf(s0v, s1v);
        float e0 = __expf(s0v - mx), e1 = __expf(s1v - mx);
        float inv = 1.0f / (e0 + e1);
        s_attn[hh * 4 + ll * 2 + 0] = e0 * inv;
        s_attn[hh * 4 + ll * 2 + 1] = e1 * inv;
    }
    __syncthreads();

    for (int i = tid; i < 2 * D; i += blockDim.x) {
        int l2 = i / D;
        int d = i - l2 * D;
        int h2 = d / HD;
        float v0 = g_qkv[0 * 3 * D + 2 * D + d];
        float v1 = g_qkv[1 * 3 * D + 2 * D + d];
        g_o[i] = s_attn[h2 * 4 + l2 * 2 + 0] * v0 +
                 s_attn[h2 * 4 + l2 * 2 + 1] * v1;
    }
}

// ---------------------------------------------------------------------------
// Stage 7: out = 0.5 * dot(g0 + g1, exp_w2) + exp_b2
// ---------------------------------------------------------------------------
__global__ void k_final(const float* __restrict__ w2,
                        const float* __restrict__ b2,
                        float* __restrict__ out) {
    __shared__ float red[32];
    float acc = 0.0f;
    for (int i = threadIdx.x; i < E; i += blockDim.x)
        acc += (g_g[i] + g_g[E + i]) * w2[i];
#pragma unroll
    for (int off = 16; off; off >>= 1) acc += __shfl_xor_sync(0xFFFFFFFFu, acc, off);
    const int warp = threadIdx.x >> 5, lane = threadIdx.x & 31;
    if (lane == 0) red[warp] = acc;
    __syncthreads();
    if (threadIdx.x == 0) {
        float s = 0.0f;
        const int nw = blockDim.x >> 5;
        for (int w = 0; w < nw; ++w) s += red[w];
        out[0] = 0.5f * s + b2[0];
    }
}

// ---------------------------------------------------------------------------
extern "C" void kernel_launch(void* const* d_in, const int* in_sizes, int n_in,
                              void* d_out, int out_size) {
    const float* ray        = (const float*)d_in[0];
    const float* emb1_w     = (const float*)d_in[1];
    const float* emb1_b     = (const float*)d_in[2];
    const float* emb2_w     = (const float*)d_in[3];
    const float* emb2_b     = (const float*)d_in[4];
    const float* attn_in_w  = (const float*)d_in[5];
    const float* attn_in_b  = (const float*)d_in[6];
    const float* attn_out_w = (const float*)d_in[7];
    const float* attn_out_b = (const float*)d_in[8];
    const float* ffn1_w     = (const float*)d_in[9];
    const float* ffn1_b     = (const float*)d_in[10];
    const float* ffn2_w     = (const float*)d_in[11];
    const float* ffn2_b     = (const float*)d_in[12];
    const float* exp_w1     = (const float*)d_in[13];
    const float* exp_b1     = (const float*)d_in[14];
    const float* exp_w2     = (const float*)d_in[15];
    const float* exp_b2     = (const float*)d_in[16];
    // d_in[17] = idx (always 0, single expert) — unused
    float* out = (float*)d_out;

    float *px, *pqkv, *po, *px1, *ph, *px2, *pg;
    cudaGetSymbolAddress((void**)&px,   g_x);
    cudaGetSymbolAddress((void**)&pqkv, g_qkv);
    cudaGetSymbolAddress((void**)&po,   g_o);
    cudaGetSymbolAddress((void**)&px1,  g_x1);
    cudaGetSymbolAddress((void**)&ph,   g_h);
    cudaGetSymbolAddress((void**)&px2,  g_x2);
    cudaGetSymbolAddress((void**)&pg,   g_g);

    const int GRID = 148 * 4;   // persistent, 4 blocks/SM

    // 0: embeddings -> g_x [2][D]
    k_embed<<<(D + 255) / 256, 256>>>(ray, emb1_w, emb1_b, emb2_w, emb2_b);

    // 1: qkv = x @ attn_in_w^T + b  -> g_qkv [2][3D]   (201 MB of weights)
    k_gemv_p<false, false><<<GRID, 256>>>(attn_in_w, attn_in_b, px, nullptr, pqkv, 3 * D);

    // 2: attention -> g_o [2][D]
    k_attn<<<1, 256>>>();

    // 3: x1 = x + o @ attn_out_w^T + b
    k_gemv_p<false, true><<<GRID, 256>>>(attn_out_w, attn_out_b, po, px, px1, D);

    // 4: h = relu(x1 @ ffn1_w^T + b1)
    k_gemv_p<true, false><<<GRID, 256>>>(ffn1_w, ffn1_b, px1, nullptr, ph, D);

    // 5: x2 = x1 + h @ ffn2_w^T + b2
    k_gemv_p<false, true><<<GRID, 256>>>(ffn2_w, ffn2_b, ph, px1, px2, D);

    // 6: g = relu(x2 @ exp_w1^T + b1)  -> [2][E]   (134 MB of weights)
    k_gemv_p<true, false><<<GRID, 256>>>(exp_w1, exp_b1, px2, nullptr, pg, E);

    // 7: out = mean over seq of (g @ exp_w2^T + b2)
    k_final<<<1, 1024>>>(exp_w2, exp_b2, out);
}